// round 15
// baseline (speedup 1.0000x reference)
#include <cuda_runtime.h>
#include <stdint.h>

#define BB   16
#define CC   512
#define NN   1024
#define HH   8
#define DD   64
#define HIDC 2048
#define NW   (NN/32)     // 32 packed words along N
#define NPART 128        // BB * (NN/128) partials per channel

// ---------------- scratch (static __device__ globals; no allocations) --------
__device__ float          g_Y [(size_t)BB*HIDC*NN];     // GEMM scratch (holds 3x qkv or fc1)
__device__ float          g_X1[(size_t)BB*CC*NN];       // residual-1 (x + proj spikes)
__device__ float          g_Part[(size_t)2*HIDC*NPART]; // stats partials [sums | sqsums]
__device__ uint32_t       g_Qw[(size_t)BB*CC*NW];       // Q spikes, bit-packed along n
__device__ uint32_t       g_Kw[(size_t)BB*CC*NW];
__device__ uint32_t       g_Vw[(size_t)BB*CC*NW];
__device__ int            g_M [(size_t)BB*HH*DD*DD];    // K^T V integer matrices
__device__ uint32_t       g_Abits [(size_t)BB*NN*(CC/32)];     // attn spikes [b][n][c/32]
__device__ uint32_t       g_H1bits[(size_t)BB*NN*(HIDC/32)];   // fc1 spikes  [b][n][c/32]
__device__ float          g_Wt[(size_t)HIDC*CC];        // transposed weights for sparse [K][O]
__device__ float          g_Wqkv3[(size_t)3*CC*CC];     // q/k/v weights k-major [l][K][O]
__device__ float          g_Wfc1t[(size_t)CC*HIDC];     // fc1 weights k-major [K][O]
__device__ float          g_mean[3*CC > HIDC ? 3*CC : HIDC];
__device__ float          g_rstd[3*CC > HIDC ? 3*CC : HIDC];

// ---------------- cp.async helpers ------------------------------------------
__device__ __forceinline__ void cp16(uint32_t s, const void* g) {
    asm volatile("cp.async.cg.shared.global [%0], [%1], 16;" :: "r"(s), "l"(g));
}
__device__ __forceinline__ void cp_commit() {
    asm volatile("cp.async.commit_group;");
}
__device__ __forceinline__ void cp_wait1() {
    asm volatile("cp.async.wait_group 1;");
}

// ---------------- fp32 dense GEMM, cp.async 3-stage, fused stats partials ----
// Y[l,b,o,n] = sum_c Wt_l[c,o] * X[b,c,n] (+bias); Wt is k-major [K][O].
// 128x128 tile, Ktile=16, 256 threads, 8x8/thread. Per-output fmaf chain is
// ascending-k sequential. Epilogue: per-channel partial (sum, sumsq) over this
// tile's 128 n values, deterministic fixed order -> Part[oc][b*8 + ntile].
template<int LAYERS>
__global__ __launch_bounds__(256, 2) void gemm_cp(
    const float* __restrict__ Wt, const float* __restrict__ X,
    const float* __restrict__ bias, float* __restrict__ Y,
    float* __restrict__ Part, int OCtot, int O, int K)
{
    __shared__ float As[3][16][128];   // [stage][k][o]
    __shared__ float Bs[3][16][128];   // [stage][k][n]

    int z = blockIdx.z;
    int b     = (LAYERS == 1) ? z : (z & (BB - 1));
    int layer = (LAYERS == 1) ? 0 : (z >> 4);
    const float* WtL = Wt + (size_t)layer * K * O;

    int o0 = blockIdx.y * 128;
    int n0 = blockIdx.x * 128;
    const float* Xb = X + (size_t)b * K * NN;
    float*       Yb = Y + ((size_t)layer * BB + b) * (size_t)O * NN;

    int tid = threadIdx.x;
    int ty = tid >> 4, tx = tid & 15;

    int f0k = tid >> 5,         f0c = (tid & 31) * 4;
    int f1k = (tid + 256) >> 5, f1c = ((tid + 256) & 31) * 4;

    uint32_t sA = (uint32_t)__cvta_generic_to_shared(&As[0][0][0]);
    uint32_t sB = (uint32_t)__cvta_generic_to_shared(&Bs[0][0][0]);
    const uint32_t STG = 16 * 128 * 4;

    auto issue = [&](int kt, int s) {
        if (kt < K) {
            cp16(sA + s*STG + (f0k*128 + f0c)*4, WtL + (size_t)(kt + f0k)*O + o0 + f0c);
            cp16(sA + s*STG + (f1k*128 + f1c)*4, WtL + (size_t)(kt + f1k)*O + o0 + f1c);
            cp16(sB + s*STG + (f0k*128 + f0c)*4, Xb  + (size_t)(kt + f0k)*NN + n0 + f0c);
            cp16(sB + s*STG + (f1k*128 + f1c)*4, Xb  + (size_t)(kt + f1k)*NN + n0 + f1c);
        }
        cp_commit();
    };

    issue(0, 0);
    issue(16, 1);

    float acc[8][8];
    #pragma unroll
    for (int i = 0; i < 8; i++)
        #pragma unroll
        for (int j = 0; j < 8; j++) acc[i][j] = 0.f;

    int s = 0;
    for (int k0 = 0; k0 < K; k0 += 16) {
        cp_wait1();
        __syncthreads();
        int snext = s + 1; if (snext == 3) snext = 0;
        int sprev = s + 2; if (sprev >= 3) sprev -= 3;
        issue(k0 + 32, sprev);

        #pragma unroll
        for (int kk = 0; kk < 16; kk++) {
            float4 a0 = *(float4*)&As[s][kk][ty * 4];
            float4 a1 = *(float4*)&As[s][kk][64 + ty * 4];
            float4 b0 = *(float4*)&Bs[s][kk][tx * 4];
            float4 b1 = *(float4*)&Bs[s][kk][64 + tx * 4];
            float av[8] = {a0.x,a0.y,a0.z,a0.w,a1.x,a1.y,a1.z,a1.w};
            float bv[8] = {b0.x,b0.y,b0.z,b0.w,b1.x,b1.y,b1.z,b1.w};
            #pragma unroll
            for (int i = 0; i < 8; i++)
                #pragma unroll
                for (int j = 0; j < 8; j++)
                    acc[i][j] = fmaf(av[i], bv[j], acc[i][j]);
        }
        s = snext;
    }

    __syncthreads();   // all fragment reads done; As reusable for reduction
    float* reds = &As[0][0][0];      // 2048 floats
    float* redq = reds + 2048;       // 2048 floats (As holds 6144)

    #pragma unroll
    for (int i = 0; i < 8; i++) {
        int r = (i < 4) ? (ty * 4 + i) : (64 + ty * 4 + (i - 4));
        int o = o0 + r;
        float bvv = bias ? bias[o] : 0.f;
        float v0 = acc[i][0]+bvv, v1 = acc[i][1]+bvv, v2 = acc[i][2]+bvv, v3 = acc[i][3]+bvv;
        float v4 = acc[i][4]+bvv, v5 = acc[i][5]+bvv, v6 = acc[i][6]+bvv, v7 = acc[i][7]+bvv;
        float4 r0 = {v0, v1, v2, v3};
        float4 r1 = {v4, v5, v6, v7};
        *(float4*)&Yb[(size_t)o * NN + n0 + tx * 4]      = r0;
        *(float4*)&Yb[(size_t)o * NN + n0 + 64 + tx * 4] = r1;
        // fixed-order partial: ascending j
        float sm = 0.f, sq = 0.f;
        sm += v0; sq = fmaf(v0, v0, sq);
        sm += v1; sq = fmaf(v1, v1, sq);
        sm += v2; sq = fmaf(v2, v2, sq);
        sm += v3; sq = fmaf(v3, v3, sq);
        sm += v4; sq = fmaf(v4, v4, sq);
        sm += v5; sq = fmaf(v5, v5, sq);
        sm += v6; sq = fmaf(v6, v6, sq);
        sm += v7; sq = fmaf(v7, v7, sq);
        reds[r * 16 + tx] = sm;
        redq[r * 16 + tx] = sq;
    }
    __syncthreads();
    if (tid < 128) {
        float sm = 0.f, sq = 0.f;
        #pragma unroll
        for (int t2 = 0; t2 < 16; t2++) {      // ascending tx: deterministic
            sm += reds[tid * 16 + t2];
            sq += redq[tid * 16 + t2];
        }
        int oc = layer * O + o0 + tid;
        int pidx = b * 8 + blockIdx.x;         // NN/128 = 8 n-tiles
        Part[(size_t)oc * NPART + pidx] = sm;
        Part[(size_t)OCtot * NPART + (size_t)oc * NPART + pidx] = sq;
    }
}

// ---------------- stats reduce: fold NPART partials per channel (fixed order)
// Fully unrolled: identical ascending-p add sequence (bitwise same results),
// but all 256 loads issued with high MLP instead of one-at-a-time.
__global__ __launch_bounds__(256) void stats_reduce(
    const float* __restrict__ Part, int OCtot,
    float* __restrict__ mean, float* __restrict__ rstd)
{
    int oc = blockIdx.x * 256 + threadIdx.x;
    if (oc >= OCtot) return;
    const float* ps = Part + (size_t)oc * NPART;
    const float* pq = Part + (size_t)OCtot * NPART + (size_t)oc * NPART;
    float s = 0.f, q = 0.f;
    #pragma unroll
    for (int p = 0; p < NPART; p++) { s += ps[p]; q += pq[p]; }
    const float cnt = (float)(BB * NN);
    float m = s / cnt;
    float v = q / cnt - m * m;
    mean[oc] = m;
    rstd[oc] = rsqrtf(v + 1e-5f);
}

// ---------------- weight transpose: Wt[k][o] = W[o][k] -----------------------
template<int LAYERS>
__global__ __launch_bounds__(256) void transpose_w(
    const float* __restrict__ W0, const float* __restrict__ W1, const float* __restrict__ W2,
    float* __restrict__ Wt, int O, int K)
{
    __shared__ float t[32][33];
    int l = (LAYERS == 1) ? 0 : blockIdx.z;
    const float* W = (l == 0) ? W0 : (l == 1) ? W1 : W2;
    float* WtL = Wt + (size_t)l * O * K;
    int k0 = blockIdx.x * 32, o0 = blockIdx.y * 32;
    int x = threadIdx.x & 31, y = threadIdx.x >> 5;
    #pragma unroll
    for (int i = 0; i < 32; i += 8)
        t[y + i][x] = W[(size_t)(o0 + y + i) * K + k0 + x];
    __syncthreads();
    #pragma unroll
    for (int i = 0; i < 32; i += 8)
        WtL[(size_t)(k0 + y + i) * O + o0 + x] = t[x][y + i];
}

// ---------------- sparse binary GEMM: Y = bias + sum_{c active} Wt[c,:] ------
__global__ __launch_bounds__(128) void sparse_gemm(
    const float* __restrict__ Wt,        // [K][512]
    const uint32_t* __restrict__ Xbits,  // [B][N][K/32]
    const float* __restrict__ bias,
    float* __restrict__ Y, int K)        // O fixed = 512
{
    const int O = CC;
    int n = blockIdx.x & (NN - 1);
    int b = blockIdx.x >> 10;
    int tid = threadIdx.x;
    int W32 = K >> 5;

    __shared__ uint16_t act[HIDC];
    __shared__ int s_cnt;

    const uint32_t* colbits = Xbits + ((size_t)b * NN + n) * W32;

    if (tid < 32) {
        int cnt = 0;
        for (int w0 = 0; w0 < W32; w0 += 32) {
            uint32_t bits = (w0 + tid < W32) ? colbits[w0 + tid] : 0u;
            int pc = __popc(bits);
            int sc = pc;
            #pragma unroll
            for (int dd = 1; dd < 32; dd <<= 1) {
                int t = __shfl_up_sync(0xffffffffu, sc, dd);
                if (tid >= dd) sc += t;
            }
            int off = cnt + sc - pc;
            int total = __shfl_sync(0xffffffffu, sc, 31);
            int base_c = (w0 + tid) * 32;
            while (bits) {
                int c = __ffs(bits) - 1;
                act[off++] = (uint16_t)(base_c + c);
                bits &= bits - 1;
            }
            cnt += total;
        }
        if (tid == 0) s_cnt = cnt;
    }
    __syncthreads();
    int cnt = s_cnt;

    int o = tid * 4;
    float4 acc;
    if (bias) acc = *(const float4*)&bias[o];
    else      acc = make_float4(0.f, 0.f, 0.f, 0.f);

    int i = 0;
    for (; i + 3 < cnt; i += 4) {
        float4 p0 = *(const float4*)&Wt[(size_t)act[i]     * O + o];
        float4 p1 = *(const float4*)&Wt[(size_t)act[i + 1] * O + o];
        float4 p2 = *(const float4*)&Wt[(size_t)act[i + 2] * O + o];
        float4 p3 = *(const float4*)&Wt[(size_t)act[i + 3] * O + o];
        acc.x += p0.x; acc.y += p0.y; acc.z += p0.z; acc.w += p0.w;
        acc.x += p1.x; acc.y += p1.y; acc.z += p1.z; acc.w += p1.w;
        acc.x += p2.x; acc.y += p2.y; acc.z += p2.z; acc.w += p2.w;
        acc.x += p3.x; acc.y += p3.y; acc.z += p3.z; acc.w += p3.w;
    }
    for (; i < cnt; i++) {
        float4 p0 = *(const float4*)&Wt[(size_t)act[i] * O + o];
        acc.x += p0.x; acc.y += p0.y; acc.z += p0.z; acc.w += p0.w;
    }

    float* Yc = Y + (size_t)b * O * NN + n;
    Yc[(size_t)(o + 0) * NN] = acc.x;
    Yc[(size_t)(o + 1) * NN] = acc.y;
    Yc[(size_t)(o + 2) * NN] = acc.z;
    Yc[(size_t)(o + 3) * NN] = acc.w;
}

// ---------------- per-channel batch stats over (B, N) (sparse outputs) -------
__global__ __launch_bounds__(256) void stats_kernel(
    const float* __restrict__ Y, int O, float* __restrict__ mean, float* __restrict__ rstd)
{
    int o = blockIdx.x;
    int tid = threadIdx.x;
    float s = 0.f, sq = 0.f;
    for (int b = 0; b < BB; b++) {
        const float* p = Y + ((size_t)b * O + o) * NN;
        for (int n = tid; n < NN; n += 256) { float v = p[n]; s += v; sq += v*v; }
    }
    __shared__ float sh0[256], sh1[256];
    sh0[tid]=s; sh1[tid]=sq; __syncthreads();
    for (int st=128; st>0; st>>=1) {
        if (tid < st) { sh0[tid]+=sh0[tid+st]; sh1[tid]+=sh1[tid+st]; }
        __syncthreads();
    }
    if (tid == 0) {
        const float cnt = (float)(BB*NN);
        float m = sh0[0]/cnt;
        float v = sh1[0]/cnt - m*m;
        mean[o] = m;
        rstd[o] = rsqrtf(v + 1e-5f);
    }
}

// ---------------- q/k/v binarize + bit-pack along n (warp ballot) ------------
__global__ __launch_bounds__(256) void bin_qkv_pack(
    const float* __restrict__ Y, const float* __restrict__ mean, const float* __restrict__ rstd,
    const float* __restrict__ qg, const float* __restrict__ qb,
    const float* __restrict__ kg, const float* __restrict__ kb,
    const float* __restrict__ vg, const float* __restrict__ vb,
    uint32_t* __restrict__ Qw, uint32_t* __restrict__ Kw, uint32_t* __restrict__ Vw)
{
    const size_t LS = (size_t)BB * CC * NN;
    size_t i = (size_t)blockIdx.x * 256 + threadIdx.x;
    int l = (int)(i / LS);
    size_t il = i - (size_t)l * LS;
    int n = (int)(il % NN);
    int c = (int)((il / NN) % CC);
    int b = (int)(il / ((size_t)CC * NN));
    int oc = l * CC + c;
    const float* g  = (l == 0) ? qg : (l == 1) ? kg : vg;
    const float* bb = (l == 0) ? qb : (l == 1) ? kb : vb;
    float z = (Y[i] - mean[oc]) * rstd[oc] * g[c] + bb[c];
    uint32_t word = __ballot_sync(0xffffffffu, z >= 2.0f);
    if ((threadIdx.x & 31) == 0) {
        uint32_t* out = (l == 0) ? Qw : (l == 1) ? Kw : Vw;
        out[((size_t)b * CC + c) * NW + (n >> 5)] = word;
    }
}

__global__ __launch_bounds__(256) void bin_resid_kernel(
    const float* __restrict__ Y, const float* __restrict__ mean, const float* __restrict__ rstd,
    const float* __restrict__ g, const float* __restrict__ bb,
    const float* __restrict__ x, float* __restrict__ X1, int O)
{
    size_t i = (size_t)blockIdx.x * 256 + threadIdx.x;
    int o = (int)((i / NN) % O);
    float z = (Y[i] - mean[o]) * rstd[o] * g[o] + bb[o];
    X1[i] = x[i] + ((z >= 2.0f) ? 1.0f : 0.0f);
}

__global__ __launch_bounds__(256) void bin_final_kernel(
    const float* __restrict__ Y, const float* __restrict__ mean, const float* __restrict__ rstd,
    const float* __restrict__ g, const float* __restrict__ bb,
    const float* __restrict__ X1, float* __restrict__ out, int O)
{
    size_t i = (size_t)blockIdx.x * 256 + threadIdx.x;
    int o = (int)((i / NN) % O);
    float z = (Y[i] - mean[o]) * rstd[o] * g[o] + bb[o];
    out[i] = X1[i] + ((z >= 2.0f) ? 1.0f : 0.0f);
}

// fc1 binarize + bit-pack (along channel): one warp per (b, c-word, n-blk-32).
__global__ __launch_bounds__(256) void bin_pack_kernel(
    const float* __restrict__ Y, const float* __restrict__ mean, const float* __restrict__ rstd,
    const float* __restrict__ g, const float* __restrict__ bb,
    uint32_t* __restrict__ Xbits)   // [B][N][HIDC/32]
{
    const int O = HIDC, W32 = HIDC / 32;
    int gw   = (blockIdx.x * blockDim.x + threadIdx.x) >> 5;
    int lane = threadIdx.x & 31;
    int nblk = gw & 31;
    int w    = (gw >> 5) & (W32 - 1);
    int b    = gw >> 11;
    int n    = nblk * 32 + lane;

    uint32_t m = 0;
    #pragma unroll 8
    for (int e = 0; e < 32; e++) {
        int o = w * 32 + e;
        float z = (Y[((size_t)b * O + o) * NN + n] - mean[o]) * rstd[o] * g[o] + bb[o];
        m |= (z >= 2.0f) ? (1u << e) : 0u;
    }
    Xbits[((size_t)b * NN + n) * W32 + w] = m;
}

// ---------------- attention phase 1 (split): partial M via int atomicAdd -----
__global__ __launch_bounds__(256) void attn_m_part(
    const uint32_t* __restrict__ Kw, const uint32_t* __restrict__ Vw,
    int* __restrict__ Mg)
{
    int chunk = blockIdx.x & 3;
    int bh = blockIdx.x >> 2;
    int b = bh >> 3, h = bh & 7;
    size_t base = ((size_t)b * CC + h * DD) * NW + chunk * 8;

    __shared__ uint32_t ks[64][9];
    __shared__ uint32_t vs[64][9];
    int tid = threadIdx.x;
    for (int w = tid; w < 64 * 8; w += 256) {
        int r = w >> 3, c = w & 7;
        ks[r][c] = Kw[base + (size_t)r * NW + c];
        vs[r][c] = Vw[base + (size_t)r * NW + c];
    }
    __syncthreads();

    int d  = tid >> 2;
    int e0 = (tid & 3) * 16;
    int* Mrow = Mg + ((size_t)bh * DD + d) * DD;
    #pragma unroll
    for (int e = 0; e < 16; e++) {
        int s = 0;
        #pragma unroll
        for (int w = 0; w < 8; w++)
            s += __popc(ks[d][w] & vs[e0 + e][w]);
        atomicAdd(&Mrow[e0 + e], s);
    }
}

// ---------------- attention phase 2: spike = (sum_d Q[d,n]*M[d][e] >= 8) -----
__global__ __launch_bounds__(256) void attn_s_kernel(
    const uint32_t* __restrict__ Qw, const int* __restrict__ Mg,
    uint32_t* __restrict__ Abits)
{
    int nc = blockIdx.x & 7;
    int h  = (blockIdx.x >> 3) & 7;
    int b  = blockIdx.x >> 6;
    int bh = b * 8 + h;

    __shared__ int Msh[64][64];
    __shared__ uint32_t qs[64][4];

    int tid = threadIdx.x;
    const int* Mp = Mg + (size_t)bh * DD * DD;
    for (int i = tid; i < 64 * 64; i += 256)
        Msh[i >> 6][i & 63] = Mp[i];
    size_t qbase = ((size_t)b * CC + h * DD) * NW + nc * 4;
    for (int i = tid; i < 64 * 4; i += 256)
        qs[i >> 2][i & 3] = Qw[qbase + (size_t)(i >> 2) * NW + (i & 3)];
    __syncthreads();

    int nl = tid & 127;
    int er = (tid >> 7) * 32;
    int widx = nl >> 5, bitp = nl & 31;

    int s[32];
    #pragma unroll
    for (int e = 0; e < 32; e++) s[e] = 0;
    for (int d = 0; d < 64; d++) {
        if ((qs[d][widx] >> bitp) & 1u) {
            #pragma unroll
            for (int e = 0; e < 32; e++) s[e] += Msh[d][er + e];
        }
    }
    uint32_t m = 0;
    #pragma unroll
    for (int e = 0; e < 32; e++) m |= (s[e] >= 8) ? (1u << e) : 0u;
    int n = nc * 128 + nl;
    Abits[((size_t)b * NN + n) * (CC / 32) + h * 2 + (er >> 5)] = m;
}

// ---------------- launch -----------------------------------------------------
extern "C" void kernel_launch(void* const* d_in, const int* in_sizes, int n_in,
                              void* d_out, int out_size)
{
    const float* x        = (const float*)d_in[0];
    const float* q_w      = (const float*)d_in[1];
    const float* q_g      = (const float*)d_in[2];
    const float* q_b      = (const float*)d_in[3];
    const float* k_w      = (const float*)d_in[4];
    const float* k_g      = (const float*)d_in[5];
    const float* k_b      = (const float*)d_in[6];
    const float* v_w      = (const float*)d_in[7];
    const float* v_g      = (const float*)d_in[8];
    const float* v_b      = (const float*)d_in[9];
    const float* proj_w   = (const float*)d_in[10];
    const float* proj_bias= (const float*)d_in[11];
    const float* proj_g   = (const float*)d_in[12];
    const float* proj_b   = (const float*)d_in[13];
    const float* fc1_w    = (const float*)d_in[14];
    const float* fc1_bias = (const float*)d_in[15];
    const float* fc1_g    = (const float*)d_in[16];
    const float* fc1_b    = (const float*)d_in[17];
    const float* fc2_w    = (const float*)d_in[18];
    const float* fc2_bias = (const float*)d_in[19];
    const float* fc2_g    = (const float*)d_in[20];
    const float* fc2_b    = (const float*)d_in[21];
    float* out = (float*)d_out;

    float *Y, *X1, *Part, *Wt, *Wqkv3, *Wfc1t, *mean, *rstd;
    uint32_t *Qw, *Kw, *Vw, *Abits, *H1bits;
    int *Mg;
    cudaGetSymbolAddress((void**)&Y,      g_Y);
    cudaGetSymbolAddress((void**)&X1,     g_X1);
    cudaGetSymbolAddress((void**)&Part,   g_Part);
    cudaGetSymbolAddress((void**)&Wt,     g_Wt);
    cudaGetSymbolAddress((void**)&Wqkv3,  g_Wqkv3);
    cudaGetSymbolAddress((void**)&Wfc1t,  g_Wfc1t);
    cudaGetSymbolAddress((void**)&mean,   g_mean);
    cudaGetSymbolAddress((void**)&rstd,   g_rstd);
    cudaGetSymbolAddress((void**)&Qw,     g_Qw);
    cudaGetSymbolAddress((void**)&Kw,     g_Kw);
    cudaGetSymbolAddress((void**)&Vw,     g_Vw);
    cudaGetSymbolAddress((void**)&Mg,     g_M);
    cudaGetSymbolAddress((void**)&Abits,  g_Abits);
    cudaGetSymbolAddress((void**)&H1bits, g_H1bits);

    dim3 blk256(256);
    int gbC = (int)(((size_t)BB*CC*NN) / 256);   // 32768

    // k-major copies of dense weights (enables cp.async A-tiles)
    transpose_w<3><<<dim3(CC/32, CC/32, 3), 256>>>(q_w, k_w, v_w, Wqkv3, CC, CC);
    transpose_w<1><<<dim3(CC/32, HIDC/32), 256>>>(fc1_w, fc1_w, fc1_w, Wfc1t, HIDC, CC);
    cudaMemsetAsync(Mg, 0, (size_t)BB*HH*DD*DD*sizeof(int));

    // Q/K/V: batched conv1x1 with fused stats partials -> reduce -> binarize
    gemm_cp<3><<<dim3(NN/128, CC/128, 3*BB), blk256>>>(Wqkv3, x, nullptr, Y, Part, 3*CC, CC, CC);
    stats_reduce<<<(3*CC + 255)/256, 256>>>(Part, 3*CC, mean, rstd);
    bin_qkv_pack<<<3*gbC, 256>>>(Y, mean, rstd, q_g, q_b, k_g, k_b, v_g, v_b, Qw, Kw, Vw);

    // Spiking attention: M = K^T V (popcount, int-atomic partials), spike(Q M)
    attn_m_part<<<BB*HH*4, 256>>>(Kw, Vw, Mg);
    attn_s_kernel<<<BB*HH*8, 256>>>(Qw, Mg, Abits);

    // proj: sparse binary GEMM -> BN -> spike -> residual 1
    transpose_w<1><<<dim3(CC/32, CC/32), 256>>>(proj_w, proj_w, proj_w, Wt, CC, CC);
    sparse_gemm<<<BB*NN, 128>>>(Wt, Abits, proj_bias, Y, CC);
    stats_kernel<<<CC, 256>>>(Y, CC, mean, rstd);
    bin_resid_kernel<<<gbC, 256>>>(Y, mean, rstd, proj_g, proj_b, x, X1, CC);

    // fc1: GEMM with fused stats partials -> reduce -> binarize (bit-packed)
    gemm_cp<1><<<dim3(NN/128, HIDC/128, BB), blk256>>>(Wfc1t, X1, fc1_bias, Y, Part, HIDC, HIDC, CC);
    stats_reduce<<<(HIDC + 255)/256, 256>>>(Part, HIDC, mean, rstd);
    bin_pack_kernel<<<(BB*(HIDC/32)*32*32)/256, 256>>>(Y, mean, rstd, fc1_g, fc1_b, H1bits);

    // fc2: sparse binary GEMM -> BN -> spike -> residual 2
    transpose_w<1><<<dim3(HIDC/32, CC/32), 256>>>(fc2_w, fc2_w, fc2_w, Wt, CC, HIDC);
    sparse_gemm<<<BB*NN, 128>>>(Wt, H1bits, fc2_bias, Y, HIDC);
    stats_kernel<<<CC, 256>>>(Y, CC, mean, rstd);
    bin_final_kernel<<<gbC, 256>>>(Y, mean, rstd, fc2_g, fc2_b, X1, out, CC);
}

// round 16
// speedup vs baseline: 1.0351x; 1.0351x over previous
#include <cuda_runtime.h>
#include <stdint.h>

#define BB   16
#define CC   512
#define NN   1024
#define HH   8
#define DD   64
#define HIDC 2048
#define NW   (NN/32)     // 32 packed words along N
#define NPART 128        // BB * (NN/128) partials per channel

// ---------------- scratch (static __device__ globals; no allocations) --------
__device__ float          g_Y [(size_t)BB*HIDC*NN];     // GEMM scratch (holds 3x qkv or fc1)
__device__ float          g_X1[(size_t)BB*CC*NN];       // residual-1 (x + proj spikes)
__device__ float          g_Part[(size_t)2*HIDC*NPART]; // stats partials [p][oc] | sq [p][oc]
__device__ uint32_t       g_Qw[(size_t)BB*CC*NW];       // Q spikes, bit-packed along n
__device__ uint32_t       g_Kw[(size_t)BB*CC*NW];
__device__ uint32_t       g_Vw[(size_t)BB*CC*NW];
__device__ int            g_M [(size_t)BB*HH*DD*DD];    // K^T V integer matrices
__device__ uint32_t       g_Abits [(size_t)BB*NN*(CC/32)];     // attn spikes [b][n][c/32]
__device__ uint32_t       g_H1bits[(size_t)BB*NN*(HIDC/32)];   // fc1 spikes  [b][n][c/32]
__device__ float          g_Wt[(size_t)HIDC*CC];        // transposed weights for sparse [K][O]
__device__ float          g_Wqkv3[(size_t)3*CC*CC];     // q/k/v weights k-major [l][K][O]
__device__ float          g_Wfc1t[(size_t)CC*HIDC];     // fc1 weights k-major [K][O]
__device__ float          g_mean[3*CC > HIDC ? 3*CC : HIDC];
__device__ float          g_rstd[3*CC > HIDC ? 3*CC : HIDC];

// ---------------- cp.async helpers ------------------------------------------
__device__ __forceinline__ void cp16(uint32_t s, const void* g) {
    asm volatile("cp.async.cg.shared.global [%0], [%1], 16;" :: "r"(s), "l"(g));
}
__device__ __forceinline__ void cp_commit() {
    asm volatile("cp.async.commit_group;");
}
__device__ __forceinline__ void cp_wait1() {
    asm volatile("cp.async.wait_group 1;");
}

// ---------------- fp32 dense GEMM, cp.async 3-stage, fused stats partials ----
// Y[l,b,o,n] = sum_c Wt_l[c,o] * X[b,c,n] (+bias); Wt is k-major [K][O].
// 128x128 tile, Ktile=16, 256 threads, 8x8/thread. Per-output fmaf chain is
// ascending-k sequential. Epilogue: per-channel partial (sum, sumsq) over this
// tile's 128 n values, deterministic fixed order -> Part[pidx][oc] (coalesced).
template<int LAYERS>
__global__ __launch_bounds__(256, 2) void gemm_cp(
    const float* __restrict__ Wt, const float* __restrict__ X,
    const float* __restrict__ bias, float* __restrict__ Y,
    float* __restrict__ Part, int OCtot, int O, int K)
{
    __shared__ float As[3][16][128];   // [stage][k][o]
    __shared__ float Bs[3][16][128];   // [stage][k][n]

    int z = blockIdx.z;
    int b     = (LAYERS == 1) ? z : (z & (BB - 1));
    int layer = (LAYERS == 1) ? 0 : (z >> 4);
    const float* WtL = Wt + (size_t)layer * K * O;

    int o0 = blockIdx.y * 128;
    int n0 = blockIdx.x * 128;
    const float* Xb = X + (size_t)b * K * NN;
    float*       Yb = Y + ((size_t)layer * BB + b) * (size_t)O * NN;

    int tid = threadIdx.x;
    int ty = tid >> 4, tx = tid & 15;

    int f0k = tid >> 5,         f0c = (tid & 31) * 4;
    int f1k = (tid + 256) >> 5, f1c = ((tid + 256) & 31) * 4;

    uint32_t sA = (uint32_t)__cvta_generic_to_shared(&As[0][0][0]);
    uint32_t sB = (uint32_t)__cvta_generic_to_shared(&Bs[0][0][0]);
    const uint32_t STG = 16 * 128 * 4;

    auto issue = [&](int kt, int s) {
        if (kt < K) {
            cp16(sA + s*STG + (f0k*128 + f0c)*4, WtL + (size_t)(kt + f0k)*O + o0 + f0c);
            cp16(sA + s*STG + (f1k*128 + f1c)*4, WtL + (size_t)(kt + f1k)*O + o0 + f1c);
            cp16(sB + s*STG + (f0k*128 + f0c)*4, Xb  + (size_t)(kt + f0k)*NN + n0 + f0c);
            cp16(sB + s*STG + (f1k*128 + f1c)*4, Xb  + (size_t)(kt + f1k)*NN + n0 + f1c);
        }
        cp_commit();
    };

    issue(0, 0);
    issue(16, 1);

    float acc[8][8];
    #pragma unroll
    for (int i = 0; i < 8; i++)
        #pragma unroll
        for (int j = 0; j < 8; j++) acc[i][j] = 0.f;

    int s = 0;
    for (int k0 = 0; k0 < K; k0 += 16) {
        cp_wait1();
        __syncthreads();
        int snext = s + 1; if (snext == 3) snext = 0;
        int sprev = s + 2; if (sprev >= 3) sprev -= 3;
        issue(k0 + 32, sprev);

        #pragma unroll
        for (int kk = 0; kk < 16; kk++) {
            float4 a0 = *(float4*)&As[s][kk][ty * 4];
            float4 a1 = *(float4*)&As[s][kk][64 + ty * 4];
            float4 b0 = *(float4*)&Bs[s][kk][tx * 4];
            float4 b1 = *(float4*)&Bs[s][kk][64 + tx * 4];
            float av[8] = {a0.x,a0.y,a0.z,a0.w,a1.x,a1.y,a1.z,a1.w};
            float bv[8] = {b0.x,b0.y,b0.z,b0.w,b1.x,b1.y,b1.z,b1.w};
            #pragma unroll
            for (int i = 0; i < 8; i++)
                #pragma unroll
                for (int j = 0; j < 8; j++)
                    acc[i][j] = fmaf(av[i], bv[j], acc[i][j]);
        }
        s = snext;
    }

    __syncthreads();   // all fragment reads done; As reusable for reduction
    float* reds = &As[0][0][0];      // 2048 floats
    float* redq = reds + 2048;       // 2048 floats (As holds 6144)

    #pragma unroll
    for (int i = 0; i < 8; i++) {
        int r = (i < 4) ? (ty * 4 + i) : (64 + ty * 4 + (i - 4));
        int o = o0 + r;
        float bvv = bias ? bias[o] : 0.f;
        float v0 = acc[i][0]+bvv, v1 = acc[i][1]+bvv, v2 = acc[i][2]+bvv, v3 = acc[i][3]+bvv;
        float v4 = acc[i][4]+bvv, v5 = acc[i][5]+bvv, v6 = acc[i][6]+bvv, v7 = acc[i][7]+bvv;
        float4 r0 = {v0, v1, v2, v3};
        float4 r1 = {v4, v5, v6, v7};
        *(float4*)&Yb[(size_t)o * NN + n0 + tx * 4]      = r0;
        *(float4*)&Yb[(size_t)o * NN + n0 + 64 + tx * 4] = r1;
        // fixed-order partial: ascending j
        float sm = 0.f, sq = 0.f;
        sm += v0; sq = fmaf(v0, v0, sq);
        sm += v1; sq = fmaf(v1, v1, sq);
        sm += v2; sq = fmaf(v2, v2, sq);
        sm += v3; sq = fmaf(v3, v3, sq);
        sm += v4; sq = fmaf(v4, v4, sq);
        sm += v5; sq = fmaf(v5, v5, sq);
        sm += v6; sq = fmaf(v6, v6, sq);
        sm += v7; sq = fmaf(v7, v7, sq);
        reds[r * 16 + tx] = sm;
        redq[r * 16 + tx] = sq;
    }
    __syncthreads();
    if (tid < 128) {
        float sm = 0.f, sq = 0.f;
        #pragma unroll
        for (int t2 = 0; t2 < 16; t2++) {      // ascending tx: deterministic
            sm += reds[tid * 16 + t2];
            sq += redq[tid * 16 + t2];
        }
        int oc = layer * O + o0 + tid;
        int pidx = b * 8 + blockIdx.x;         // NN/128 = 8 n-tiles
        // [p][oc] layout: coalesced writes here, coalesced reads in reduce
        Part[(size_t)pidx * OCtot + oc] = sm;
        Part[(size_t)NPART * OCtot + (size_t)pidx * OCtot + oc] = sq;
    }
}

// ---------------- stats reduce: fold NPART partials per channel (fixed order)
// [p][oc] layout: lane oc reads consecutive addresses -> 1 wavefront per load.
// Ascending-p add order preserved -> bitwise-identical mean/rstd.
__global__ __launch_bounds__(256) void stats_reduce(
    const float* __restrict__ Part, int OCtot,
    float* __restrict__ mean, float* __restrict__ rstd)
{
    int oc = blockIdx.x * 256 + threadIdx.x;
    if (oc >= OCtot) return;
    const float* ps = Part + oc;
    const float* pq = Part + (size_t)NPART * OCtot + oc;
    float s = 0.f, q = 0.f;
    #pragma unroll
    for (int p = 0; p < NPART; p++) {
        s += ps[(size_t)p * OCtot];
        q += pq[(size_t)p * OCtot];
    }
    const float cnt = (float)(BB * NN);
    float m = s / cnt;
    float v = q / cnt - m * m;
    mean[oc] = m;
    rstd[oc] = rsqrtf(v + 1e-5f);
}

// ---------------- weight transpose: Wt[k][o] = W[o][k] -----------------------
template<int LAYERS>
__global__ __launch_bounds__(256) void transpose_w(
    const float* __restrict__ W0, const float* __restrict__ W1, const float* __restrict__ W2,
    float* __restrict__ Wt, int O, int K)
{
    __shared__ float t[32][33];
    int l = (LAYERS == 1) ? 0 : blockIdx.z;
    const float* W = (l == 0) ? W0 : (l == 1) ? W1 : W2;
    float* WtL = Wt + (size_t)l * O * K;
    int k0 = blockIdx.x * 32, o0 = blockIdx.y * 32;
    int x = threadIdx.x & 31, y = threadIdx.x >> 5;
    #pragma unroll
    for (int i = 0; i < 32; i += 8)
        t[y + i][x] = W[(size_t)(o0 + y + i) * K + k0 + x];
    __syncthreads();
    #pragma unroll
    for (int i = 0; i < 32; i += 8)
        WtL[(size_t)(k0 + y + i) * O + o0 + x] = t[x][y + i];
}

// ---------------- sparse binary GEMM: Y = bias + sum_{c active} Wt[c,:] ------
__global__ __launch_bounds__(128) void sparse_gemm(
    const float* __restrict__ Wt,        // [K][512]
    const uint32_t* __restrict__ Xbits,  // [B][N][K/32]
    const float* __restrict__ bias,
    float* __restrict__ Y, int K)        // O fixed = 512
{
    const int O = CC;
    int n = blockIdx.x & (NN - 1);
    int b = blockIdx.x >> 10;
    int tid = threadIdx.x;
    int W32 = K >> 5;

    __shared__ uint16_t act[HIDC];
    __shared__ int s_cnt;

    const uint32_t* colbits = Xbits + ((size_t)b * NN + n) * W32;

    if (tid < 32) {
        int cnt = 0;
        for (int w0 = 0; w0 < W32; w0 += 32) {
            uint32_t bits = (w0 + tid < W32) ? colbits[w0 + tid] : 0u;
            int pc = __popc(bits);
            int sc = pc;
            #pragma unroll
            for (int dd = 1; dd < 32; dd <<= 1) {
                int t = __shfl_up_sync(0xffffffffu, sc, dd);
                if (tid >= dd) sc += t;
            }
            int off = cnt + sc - pc;
            int total = __shfl_sync(0xffffffffu, sc, 31);
            int base_c = (w0 + tid) * 32;
            while (bits) {
                int c = __ffs(bits) - 1;
                act[off++] = (uint16_t)(base_c + c);
                bits &= bits - 1;
            }
            cnt += total;
        }
        if (tid == 0) s_cnt = cnt;
    }
    __syncthreads();
    int cnt = s_cnt;

    int o = tid * 4;
    float4 acc;
    if (bias) acc = *(const float4*)&bias[o];
    else      acc = make_float4(0.f, 0.f, 0.f, 0.f);

    int i = 0;
    for (; i + 3 < cnt; i += 4) {
        float4 p0 = *(const float4*)&Wt[(size_t)act[i]     * O + o];
        float4 p1 = *(const float4*)&Wt[(size_t)act[i + 1] * O + o];
        float4 p2 = *(const float4*)&Wt[(size_t)act[i + 2] * O + o];
        float4 p3 = *(const float4*)&Wt[(size_t)act[i + 3] * O + o];
        acc.x += p0.x; acc.y += p0.y; acc.z += p0.z; acc.w += p0.w;
        acc.x += p1.x; acc.y += p1.y; acc.z += p1.z; acc.w += p1.w;
        acc.x += p2.x; acc.y += p2.y; acc.z += p2.z; acc.w += p2.w;
        acc.x += p3.x; acc.y += p3.y; acc.z += p3.z; acc.w += p3.w;
    }
    for (; i < cnt; i++) {
        float4 p0 = *(const float4*)&Wt[(size_t)act[i] * O + o];
        acc.x += p0.x; acc.y += p0.y; acc.z += p0.z; acc.w += p0.w;
    }

    float* Yc = Y + (size_t)b * O * NN + n;
    Yc[(size_t)(o + 0) * NN] = acc.x;
    Yc[(size_t)(o + 1) * NN] = acc.y;
    Yc[(size_t)(o + 2) * NN] = acc.z;
    Yc[(size_t)(o + 3) * NN] = acc.w;
}

// ---------------- per-channel batch stats over (B, N) (sparse outputs) -------
__global__ __launch_bounds__(256) void stats_kernel(
    const float* __restrict__ Y, int O, float* __restrict__ mean, float* __restrict__ rstd)
{
    int o = blockIdx.x;
    int tid = threadIdx.x;
    float s = 0.f, sq = 0.f;
    for (int b = 0; b < BB; b++) {
        const float* p = Y + ((size_t)b * O + o) * NN;
        for (int n = tid; n < NN; n += 256) { float v = p[n]; s += v; sq += v*v; }
    }
    __shared__ float sh0[256], sh1[256];
    sh0[tid]=s; sh1[tid]=sq; __syncthreads();
    for (int st=128; st>0; st>>=1) {
        if (tid < st) { sh0[tid]+=sh0[tid+st]; sh1[tid]+=sh1[tid+st]; }
        __syncthreads();
    }
    if (tid == 0) {
        const float cnt = (float)(BB*NN);
        float m = sh0[0]/cnt;
        float v = sh1[0]/cnt - m*m;
        mean[o] = m;
        rstd[o] = rsqrtf(v + 1e-5f);
    }
}

// ---------------- q/k/v binarize + bit-pack along n (warp ballot) ------------
__global__ __launch_bounds__(256) void bin_qkv_pack(
    const float* __restrict__ Y, const float* __restrict__ mean, const float* __restrict__ rstd,
    const float* __restrict__ qg, const float* __restrict__ qb,
    const float* __restrict__ kg, const float* __restrict__ kb,
    const float* __restrict__ vg, const float* __restrict__ vb,
    uint32_t* __restrict__ Qw, uint32_t* __restrict__ Kw, uint32_t* __restrict__ Vw)
{
    const size_t LS = (size_t)BB * CC * NN;
    size_t i = (size_t)blockIdx.x * 256 + threadIdx.x;
    int l = (int)(i / LS);
    size_t il = i - (size_t)l * LS;
    int n = (int)(il % NN);
    int c = (int)((il / NN) % CC);
    int b = (int)(il / ((size_t)CC * NN));
    int oc = l * CC + c;
    const float* g  = (l == 0) ? qg : (l == 1) ? kg : vg;
    const float* bb = (l == 0) ? qb : (l == 1) ? kb : vb;
    float z = (Y[i] - mean[oc]) * rstd[oc] * g[c] + bb[c];
    uint32_t word = __ballot_sync(0xffffffffu, z >= 2.0f);
    if ((threadIdx.x & 31) == 0) {
        uint32_t* out = (l == 0) ? Qw : (l == 1) ? Kw : Vw;
        out[((size_t)b * CC + c) * NW + (n >> 5)] = word;
    }
}

__global__ __launch_bounds__(256) void bin_resid_kernel(
    const float* __restrict__ Y, const float* __restrict__ mean, const float* __restrict__ rstd,
    const float* __restrict__ g, const float* __restrict__ bb,
    const float* __restrict__ x, float* __restrict__ X1, int O)
{
    size_t i = (size_t)blockIdx.x * 256 + threadIdx.x;
    int o = (int)((i / NN) % O);
    float z = (Y[i] - mean[o]) * rstd[o] * g[o] + bb[o];
    X1[i] = x[i] + ((z >= 2.0f) ? 1.0f : 0.0f);
}

__global__ __launch_bounds__(256) void bin_final_kernel(
    const float* __restrict__ Y, const float* __restrict__ mean, const float* __restrict__ rstd,
    const float* __restrict__ g, const float* __restrict__ bb,
    const float* __restrict__ X1, float* __restrict__ out, int O)
{
    size_t i = (size_t)blockIdx.x * 256 + threadIdx.x;
    int o = (int)((i / NN) % O);
    float z = (Y[i] - mean[o]) * rstd[o] * g[o] + bb[o];
    out[i] = X1[i] + ((z >= 2.0f) ? 1.0f : 0.0f);
}

// fc1 binarize + bit-pack (along channel): one warp per (b, c-word, n-blk-32).
__global__ __launch_bounds__(256) void bin_pack_kernel(
    const float* __restrict__ Y, const float* __restrict__ mean, const float* __restrict__ rstd,
    const float* __restrict__ g, const float* __restrict__ bb,
    uint32_t* __restrict__ Xbits)   // [B][N][HIDC/32]
{
    const int O = HIDC, W32 = HIDC / 32;
    int gw   = (blockIdx.x * blockDim.x + threadIdx.x) >> 5;
    int lane = threadIdx.x & 31;
    int nblk = gw & 31;
    int w    = (gw >> 5) & (W32 - 1);
    int b    = gw >> 11;
    int n    = nblk * 32 + lane;

    uint32_t m = 0;
    #pragma unroll 8
    for (int e = 0; e < 32; e++) {
        int o = w * 32 + e;
        float z = (Y[((size_t)b * O + o) * NN + n] - mean[o]) * rstd[o] * g[o] + bb[o];
        m |= (z >= 2.0f) ? (1u << e) : 0u;
    }
    Xbits[((size_t)b * NN + n) * W32 + w] = m;
}

// ---------------- attention phase 1 (split): partial M via int atomicAdd -----
__global__ __launch_bounds__(256) void attn_m_part(
    const uint32_t* __restrict__ Kw, const uint32_t* __restrict__ Vw,
    int* __restrict__ Mg)
{
    int chunk = blockIdx.x & 3;
    int bh = blockIdx.x >> 2;
    int b = bh >> 3, h = bh & 7;
    size_t base = ((size_t)b * CC + h * DD) * NW + chunk * 8;

    __shared__ uint32_t ks[64][9];
    __shared__ uint32_t vs[64][9];
    int tid = threadIdx.x;
    for (int w = tid; w < 64 * 8; w += 256) {
        int r = w >> 3, c = w & 7;
        ks[r][c] = Kw[base + (size_t)r * NW + c];
        vs[r][c] = Vw[base + (size_t)r * NW + c];
    }
    __syncthreads();

    int d  = tid >> 2;
    int e0 = (tid & 3) * 16;
    int* Mrow = Mg + ((size_t)bh * DD + d) * DD;
    #pragma unroll
    for (int e = 0; e < 16; e++) {
        int s = 0;
        #pragma unroll
        for (int w = 0; w < 8; w++)
            s += __popc(ks[d][w] & vs[e0 + e][w]);
        atomicAdd(&Mrow[e0 + e], s);
    }
}

// ---------------- attention phase 2: spike = (sum_d Q[d,n]*M[d][e] >= 8) -----
__global__ __launch_bounds__(256) void attn_s_kernel(
    const uint32_t* __restrict__ Qw, const int* __restrict__ Mg,
    uint32_t* __restrict__ Abits)
{
    int nc = blockIdx.x & 7;
    int h  = (blockIdx.x >> 3) & 7;
    int b  = blockIdx.x >> 6;
    int bh = b * 8 + h;

    __shared__ int Msh[64][64];
    __shared__ uint32_t qs[64][4];

    int tid = threadIdx.x;
    const int* Mp = Mg + (size_t)bh * DD * DD;
    for (int i = tid; i < 64 * 64; i += 256)
        Msh[i >> 6][i & 63] = Mp[i];
    size_t qbase = ((size_t)b * CC + h * DD) * NW + nc * 4;
    for (int i = tid; i < 64 * 4; i += 256)
        qs[i >> 2][i & 3] = Qw[qbase + (size_t)(i >> 2) * NW + (i & 3)];
    __syncthreads();

    int nl = tid & 127;
    int er = (tid >> 7) * 32;
    int widx = nl >> 5, bitp = nl & 31;

    int s[32];
    #pragma unroll
    for (int e = 0; e < 32; e++) s[e] = 0;
    for (int d = 0; d < 64; d++) {
        if ((qs[d][widx] >> bitp) & 1u) {
            #pragma unroll
            for (int e = 0; e < 32; e++) s[e] += Msh[d][er + e];
        }
    }
    uint32_t m = 0;
    #pragma unroll
    for (int e = 0; e < 32; e++) m |= (s[e] >= 8) ? (1u << e) : 0u;
    int n = nc * 128 + nl;
    Abits[((size_t)b * NN + n) * (CC / 32) + h * 2 + (er >> 5)] = m;
}

// ---------------- launch -----------------------------------------------------
extern "C" void kernel_launch(void* const* d_in, const int* in_sizes, int n_in,
                              void* d_out, int out_size)
{
    const float* x        = (const float*)d_in[0];
    const float* q_w      = (const float*)d_in[1];
    const float* q_g      = (const float*)d_in[2];
    const float* q_b      = (const float*)d_in[3];
    const float* k_w      = (const float*)d_in[4];
    const float* k_g      = (const float*)d_in[5];
    const float* k_b      = (const float*)d_in[6];
    const float* v_w      = (const float*)d_in[7];
    const float* v_g      = (const float*)d_in[8];
    const float* v_b      = (const float*)d_in[9];
    const float* proj_w   = (const float*)d_in[10];
    const float* proj_bias= (const float*)d_in[11];
    const float* proj_g   = (const float*)d_in[12];
    const float* proj_b   = (const float*)d_in[13];
    const float* fc1_w    = (const float*)d_in[14];
    const float* fc1_bias = (const float*)d_in[15];
    const float* fc1_g    = (const float*)d_in[16];
    const float* fc1_b    = (const float*)d_in[17];
    const float* fc2_w    = (const float*)d_in[18];
    const float* fc2_bias = (const float*)d_in[19];
    const float* fc2_g    = (const float*)d_in[20];
    const float* fc2_b    = (const float*)d_in[21];
    float* out = (float*)d_out;

    float *Y, *X1, *Part, *Wt, *Wqkv3, *Wfc1t, *mean, *rstd;
    uint32_t *Qw, *Kw, *Vw, *Abits, *H1bits;
    int *Mg;
    cudaGetSymbolAddress((void**)&Y,      g_Y);
    cudaGetSymbolAddress((void**)&X1,     g_X1);
    cudaGetSymbolAddress((void**)&Part,   g_Part);
    cudaGetSymbolAddress((void**)&Wt,     g_Wt);
    cudaGetSymbolAddress((void**)&Wqkv3,  g_Wqkv3);
    cudaGetSymbolAddress((void**)&Wfc1t,  g_Wfc1t);
    cudaGetSymbolAddress((void**)&mean,   g_mean);
    cudaGetSymbolAddress((void**)&rstd,   g_rstd);
    cudaGetSymbolAddress((void**)&Qw,     g_Qw);
    cudaGetSymbolAddress((void**)&Kw,     g_Kw);
    cudaGetSymbolAddress((void**)&Vw,     g_Vw);
    cudaGetSymbolAddress((void**)&Mg,     g_M);
    cudaGetSymbolAddress((void**)&Abits,  g_Abits);
    cudaGetSymbolAddress((void**)&H1bits, g_H1bits);

    dim3 blk256(256);
    int gbC = (int)(((size_t)BB*CC*NN) / 256);   // 32768

    // k-major copies of dense weights (enables cp.async A-tiles)
    transpose_w<3><<<dim3(CC/32, CC/32, 3), 256>>>(q_w, k_w, v_w, Wqkv3, CC, CC);
    transpose_w<1><<<dim3(CC/32, HIDC/32), 256>>>(fc1_w, fc1_w, fc1_w, Wfc1t, HIDC, CC);
    cudaMemsetAsync(Mg, 0, (size_t)BB*HH*DD*DD*sizeof(int));

    // Q/K/V: batched conv1x1 with fused stats partials -> reduce -> binarize
    gemm_cp<3><<<dim3(NN/128, CC/128, 3*BB), blk256>>>(Wqkv3, x, nullptr, Y, Part, 3*CC, CC, CC);
    stats_reduce<<<(3*CC + 255)/256, 256>>>(Part, 3*CC, mean, rstd);
    bin_qkv_pack<<<3*gbC, 256>>>(Y, mean, rstd, q_g, q_b, k_g, k_b, v_g, v_b, Qw, Kw, Vw);

    // Spiking attention: M = K^T V (popcount, int-atomic partials), spike(Q M)
    attn_m_part<<<BB*HH*4, 256>>>(Kw, Vw, Mg);
    attn_s_kernel<<<BB*HH*8, 256>>>(Qw, Mg, Abits);

    // proj: sparse binary GEMM -> BN -> spike -> residual 1
    transpose_w<1><<<dim3(CC/32, CC/32), 256>>>(proj_w, proj_w, proj_w, Wt, CC, CC);
    sparse_gemm<<<BB*NN, 128>>>(Wt, Abits, proj_bias, Y, CC);
    stats_kernel<<<CC, 256>>>(Y, CC, mean, rstd);
    bin_resid_kernel<<<gbC, 256>>>(Y, mean, rstd, proj_g, proj_b, x, X1, CC);

    // fc1: GEMM with fused stats partials -> reduce -> binarize (bit-packed)
    gemm_cp<1><<<dim3(NN/128, HIDC/128, BB), blk256>>>(Wfc1t, X1, fc1_bias, Y, Part, HIDC, HIDC, CC);
    stats_reduce<<<(HIDC + 255)/256, 256>>>(Part, HIDC, mean, rstd);
    bin_pack_kernel<<<(BB*(HIDC/32)*32*32)/256, 256>>>(Y, mean, rstd, fc1_g, fc1_b, H1bits);

    // fc2: sparse binary GEMM -> BN -> spike -> residual 2
    transpose_w<1><<<dim3(HIDC/32, CC/32), 256>>>(fc2_w, fc2_w, fc2_w, Wt, CC, HIDC);
    sparse_gemm<<<BB*NN, 128>>>(Wt, H1bits, fc2_bias, Y, HIDC);
    stats_kernel<<<CC, 256>>>(Y, CC, mean, rstd);
    bin_final_kernel<<<gbC, 256>>>(Y, mean, rstd, fc2_g, fc2_b, X1, out, CC);
}